// round 1
// baseline (speedup 1.0000x reference)
#include <cuda_runtime.h>
#include <math.h>
#include <stddef.h>

// Problem constants
#define Bc 8
#define Tc 2048
#define Cc 1024
#define Hc 16
#define Nn 64
#define CHUNKc 256
#define NCHUNK (Tc / CHUNKc)
#define BT (Bc * Tc)                 // 16384
#define BTC ((size_t)Bc * Tc * Cc)   // 16,777,216

// ---------------------------------------------------------------------------
// Scratch (device globals; allocation in kernel_launch is forbidden)
// ---------------------------------------------------------------------------
__device__ float g_xr[BTC];
__device__ float g_xk[BTC];
__device__ float g_xv[BTC];
__device__ float g_r[BTC];
__device__ float g_k[BTC];
__device__ float g_v[BTC];
__device__ float g_y[BTC];
__device__ float g_y2[BTC];

// ---------------------------------------------------------------------------
// Kernel 1: volatility gating + time-shift + maa mixing
//   xg[b,t,c]   = x * sigmoid(vol[b,t]*Wvol[c] + bvol[c])
//   xx          = xg[b,t-1,c] - xg[b,t,c]   (zero-pad at t=0)
//   xk/xv/xr    = xg + xx * maa_{k,v,r}[c]
// ---------------------------------------------------------------------------
__global__ __launch_bounds__(256) void prep_kernel(
    const float* __restrict__ x, const float* __restrict__ vol,
    const float* __restrict__ Wvol, const float* __restrict__ bvol,
    const float* __restrict__ mk, const float* __restrict__ mv,
    const float* __restrict__ mr)
{
    size_t idx = (size_t)blockIdx.x * 256 + threadIdx.x;
    int c = (int)(idx & (Cc - 1));
    size_t bt = idx >> 10;           // Cc = 1024
    int t = (int)(bt & (Tc - 1));

    float wv = Wvol[c];
    float bb = bvol[c];
    float vg = vol[bt];
    float g = 1.0f / (1.0f + expf(-(vg * wv + bb)));
    float xc = x[idx] * g;

    float xp = 0.0f;
    if (t > 0) {
        float vpv = vol[bt - 1];
        float gp = 1.0f / (1.0f + expf(-(vpv * wv + bb)));
        xp = x[idx - Cc] * gp;
    }
    float xx = xp - xc;
    g_xk[idx] = xc + xx * mk[c];
    g_xv[idx] = xc + xx * mv[c];
    g_xr[idx] = xc + xx * mr[c];
}

// ---------------------------------------------------------------------------
// Kernel 2: SGEMM  C[M,N] = A[M,K] * W[N,K]^T  (NT, both row-major K-major)
// 128x128 block tile, BK=8, 8x8 per-thread microtile, 256 threads,
// double-buffered shared memory.
// ---------------------------------------------------------------------------
#define GBM 128
#define GBN 128
#define GBK 8
#define SMS 132   // smem row stride (132*4 = 528 bytes, 16B aligned)

__global__ __launch_bounds__(256) void sgemm_nt(
    const float* __restrict__ A, const float* __restrict__ W,
    float* __restrict__ C, int M, int N, int K)
{
    __shared__ float As[2][GBK][SMS];
    __shared__ float Bs[2][GBK][SMS];

    const int tid = threadIdx.x;
    const int bm = blockIdx.y * GBM;
    const int bn = blockIdx.x * GBN;

    // global load mapping: 128 rows x 8 cols = 256 float4 -> 1 float4/thread/matrix
    const int lrow = tid >> 1;          // 0..127
    const int lcol = (tid & 1) << 2;    // 0 or 4
    const float* Ap = A + (size_t)(bm + lrow) * K + lcol;
    const float* Wp = W + (size_t)(bn + lrow) * K + lcol;

    // compute mapping: 16x16 thread grid, 8x8 microtile
    const int trow = (tid >> 4) << 3;   // 0..120
    const int tcol = (tid & 15) << 3;   // 0..120

    float acc[8][8];
#pragma unroll
    for (int i = 0; i < 8; i++)
#pragma unroll
        for (int j = 0; j < 8; j++) acc[i][j] = 0.0f;

    // prologue: tile 0
    {
        float4 av = *(const float4*)Ap;
        float4 wv = *(const float4*)Wp;
        As[0][lcol + 0][lrow] = av.x; As[0][lcol + 1][lrow] = av.y;
        As[0][lcol + 2][lrow] = av.z; As[0][lcol + 3][lrow] = av.w;
        Bs[0][lcol + 0][lrow] = wv.x; Bs[0][lcol + 1][lrow] = wv.y;
        Bs[0][lcol + 2][lrow] = wv.z; Bs[0][lcol + 3][lrow] = wv.w;
    }
    __syncthreads();

    const int nk = K >> 3;
    for (int kt = 0; kt < nk; kt++) {
        const int cur = kt & 1;
        float4 av2, wv2;
        const bool pf = (kt + 1 < nk);
        if (pf) {
            av2 = *(const float4*)(Ap + (size_t)(kt + 1) * GBK);
            wv2 = *(const float4*)(Wp + (size_t)(kt + 1) * GBK);
        }
#pragma unroll
        for (int kk = 0; kk < GBK; kk++) {
            float a[8], b[8];
            *(float4*)&a[0] = *(const float4*)&As[cur][kk][trow];
            *(float4*)&a[4] = *(const float4*)&As[cur][kk][trow + 4];
            *(float4*)&b[0] = *(const float4*)&Bs[cur][kk][tcol];
            *(float4*)&b[4] = *(const float4*)&Bs[cur][kk][tcol + 4];
#pragma unroll
            for (int i = 0; i < 8; i++)
#pragma unroll
                for (int j = 0; j < 8; j++) acc[i][j] += a[i] * b[j];
        }
        if (pf) {
            const int nxt = cur ^ 1;
            As[nxt][lcol + 0][lrow] = av2.x; As[nxt][lcol + 1][lrow] = av2.y;
            As[nxt][lcol + 2][lrow] = av2.z; As[nxt][lcol + 3][lrow] = av2.w;
            Bs[nxt][lcol + 0][lrow] = wv2.x; Bs[nxt][lcol + 1][lrow] = wv2.y;
            Bs[nxt][lcol + 2][lrow] = wv2.z; Bs[nxt][lcol + 3][lrow] = wv2.w;
        }
        __syncthreads();
    }

#pragma unroll
    for (int i = 0; i < 8; i++) {
        float* cp = C + (size_t)(bm + trow + i) * N + bn + tcol;
        float4 o0 = make_float4(acc[i][0], acc[i][1], acc[i][2], acc[i][3]);
        float4 o1 = make_float4(acc[i][4], acc[i][5], acc[i][6], acc[i][7]);
        *(float4*)cp = o0;
        *(float4*)(cp + 4) = o1;
    }
}

// ---------------------------------------------------------------------------
// Kernel 3: chunked linear-attention recurrence.
// Key identity (no intra-chunk mask in reference):
//   y_c     = w * R_c @ (state + K_c^T V_c)
//   state'  = w * (state + K_c^T V_c)
// One block per (b,h); state kept in registers (4x4 per thread), M in smem.
// ---------------------------------------------------------------------------
#define ATS 68  // smem row stride for 64-wide tiles
__global__ __launch_bounds__(256) void attn_kernel(
    const float* __restrict__ r, const float* __restrict__ k,
    const float* __restrict__ v, float* __restrict__ y,
    const float* __restrict__ time_decay)
{
    extern __shared__ float sm[];
    float* sA = sm;                 // 64 x ATS : K tile, then reused for R tile
    float* sV = sm + 64 * ATS;      // 64 x ATS : V tile
    float* sM = sm + 2 * 64 * ATS;  // 64 x ATS : M = state + K^T V

    const int bh = blockIdx.x;
    const int b = bh >> 4;          // H = 16
    const int h = bh & 15;
    const float w = expf(-expf(time_decay[h]));

    const int tid = threadIdx.x;
    const int i0 = (tid >> 4) << 2;  // 0..60
    const int j0 = (tid & 15) << 2;  // 0..60
    const size_t base = (size_t)b * Tc * Cc + (size_t)h * Nn;

    float st[4][4];
#pragma unroll
    for (int i = 0; i < 4; i++)
#pragma unroll
        for (int j = 0; j < 4; j++) st[i][j] = 0.0f;

    for (int c = 0; c < NCHUNK; c++) {
        const size_t cbase = base + (size_t)c * CHUNKc * Cc;

        // ---- S = K_c^T V_c (accumulate over 4 sub-tiles of 64 rows) ----
        float S[4][4];
#pragma unroll
        for (int i = 0; i < 4; i++)
#pragma unroll
            for (int j = 0; j < 4; j++) S[i][j] = 0.0f;

        for (int tb = 0; tb < 4; tb++) {
            const size_t tbase = cbase + (size_t)tb * 64 * Cc;
#pragma unroll
            for (int i = 0; i < 16; i++) {
                int idx = i * 256 + tid;
                int row = idx >> 6, col = idx & 63;
                sA[row * ATS + col] = k[tbase + (size_t)row * Cc + col];
                sV[row * ATS + col] = v[tbase + (size_t)row * Cc + col];
            }
            __syncthreads();
#pragma unroll 4
            for (int tt = 0; tt < 64; tt++) {
                float kk_[4], vv_[4];
#pragma unroll
                for (int i = 0; i < 4; i++) kk_[i] = sA[tt * ATS + i0 + i];
#pragma unroll
                for (int j = 0; j < 4; j++) vv_[j] = sV[tt * ATS + j0 + j];
#pragma unroll
                for (int i = 0; i < 4; i++)
#pragma unroll
                    for (int j = 0; j < 4; j++) S[i][j] += kk_[i] * vv_[j];
            }
            __syncthreads();
        }

        // ---- M = state + S (to smem); state = w * M ----
#pragma unroll
        for (int i = 0; i < 4; i++)
#pragma unroll
            for (int j = 0; j < 4; j++) {
                float m = st[i][j] + S[i][j];
                sM[(i0 + i) * ATS + j0 + j] = m;
                st[i][j] = w * m;
            }
        __syncthreads();

        // ---- y = w * R_c @ M  (4 sub-tiles of 64 rows) ----
        for (int tp = 0; tp < 4; tp++) {
            const size_t tbase = cbase + (size_t)tp * 64 * Cc;
#pragma unroll
            for (int i = 0; i < 16; i++) {
                int idx = i * 256 + tid;
                int row = idx >> 6, col = idx & 63;
                sA[row * ATS + col] = r[tbase + (size_t)row * Cc + col];
            }
            __syncthreads();
            float acc[4][4];
#pragma unroll
            for (int i = 0; i < 4; i++)
#pragma unroll
                for (int j = 0; j < 4; j++) acc[i][j] = 0.0f;
#pragma unroll 4
            for (int n = 0; n < 64; n++) {
                float rr[4], mm[4];
#pragma unroll
                for (int i = 0; i < 4; i++) rr[i] = sA[(i0 + i) * ATS + n];
#pragma unroll
                for (int j = 0; j < 4; j++) mm[j] = sM[n * ATS + j0 + j];
#pragma unroll
                for (int i = 0; i < 4; i++)
#pragma unroll
                    for (int j = 0; j < 4; j++) acc[i][j] += rr[i] * mm[j];
            }
#pragma unroll
            for (int i = 0; i < 4; i++)
#pragma unroll
                for (int j = 0; j < 4; j++)
                    y[tbase + (size_t)(i0 + i) * Cc + j0 + j] = w * acc[i][j];
            __syncthreads();
        }
    }
}

// ---------------------------------------------------------------------------
// Kernel 4: GroupNorm over H=16 groups of 64 channels. One warp per group.
// ---------------------------------------------------------------------------
__global__ __launch_bounds__(256) void gn_kernel(
    const float* __restrict__ y, float* __restrict__ y2,
    const float* __restrict__ gw, const float* __restrict__ gb)
{
    int g = blockIdx.x * 8 + (threadIdx.x >> 5);   // group id in [0, B*T*H)
    int lane = threadIdx.x & 31;
    size_t basei = (size_t)g * 64;
    float v0 = y[basei + lane];
    float v1 = y[basei + 32 + lane];
    float s = v0 + v1;
    float q = v0 * v0 + v1 * v1;
#pragma unroll
    for (int o = 16; o > 0; o >>= 1) {
        s += __shfl_xor_sync(0xffffffffu, s, o);
        q += __shfl_xor_sync(0xffffffffu, q, o);
    }
    float mean = s * (1.0f / 64.0f);
    float var = q * (1.0f / 64.0f) - mean * mean;
    float rstd = rsqrtf(var + 1e-5f);
    int h = g & 15;
    int cb = h * 64;
    y2[basei + lane] = (v0 - mean) * rstd * gw[cb + lane] + gb[cb + lane];
    y2[basei + 32 + lane] = (v1 - mean) * rstd * gw[cb + 32 + lane] + gb[cb + 32 + lane];
}

// ---------------------------------------------------------------------------
// Host launcher
// ---------------------------------------------------------------------------
extern "C" void kernel_launch(void* const* d_in, const int* in_sizes, int n_in,
                              void* d_out, int out_size)
{
    const float* x    = (const float*)d_in[0];
    const float* vol  = (const float*)d_in[1];
    const float* Wvol = (const float*)d_in[2];
    const float* bvol = (const float*)d_in[3];
    const float* mk   = (const float*)d_in[4];
    const float* mv   = (const float*)d_in[5];
    const float* mr   = (const float*)d_in[6];
    const float* td   = (const float*)d_in[7];
    const float* Wk   = (const float*)d_in[8];
    const float* Wv   = (const float*)d_in[9];
    const float* Wr   = (const float*)d_in[10];
    const float* Wo   = (const float*)d_in[11];
    const float* gw   = (const float*)d_in[12];
    const float* gb   = (const float*)d_in[13];
    float* out = (float*)d_out;

    float *xr, *xk, *xv, *rp, *kp, *vp, *yp, *y2p;
    cudaGetSymbolAddress((void**)&xr,  g_xr);
    cudaGetSymbolAddress((void**)&xk,  g_xk);
    cudaGetSymbolAddress((void**)&xv,  g_xv);
    cudaGetSymbolAddress((void**)&rp,  g_r);
    cudaGetSymbolAddress((void**)&kp,  g_k);
    cudaGetSymbolAddress((void**)&vp,  g_v);
    cudaGetSymbolAddress((void**)&yp,  g_y);
    cudaGetSymbolAddress((void**)&y2p, g_y2);

    // prep: gating + shift + mix
    prep_kernel<<<(unsigned)(BTC / 256), 256>>>(x, vol, Wvol, bvol, mk, mv, mr);

    // r/k/v projections: (16384 x 1024) @ (1024 x 1024)^T
    dim3 gg(Cc / GBN, BT / GBM);
    sgemm_nt<<<gg, 256>>>(xr, Wr, rp, BT, Cc, Cc);
    sgemm_nt<<<gg, 256>>>(xk, Wk, kp, BT, Cc, Cc);
    sgemm_nt<<<gg, 256>>>(xv, Wv, vp, BT, Cc, Cc);

    // chunked recurrence
    int attn_smem = 3 * 64 * ATS * sizeof(float);  // 52224 bytes
    cudaFuncSetAttribute(attn_kernel, cudaFuncAttributeMaxDynamicSharedMemorySize,
                         attn_smem);
    attn_kernel<<<Bc * Hc, 256, attn_smem>>>(rp, kp, vp, yp, td);

    // GroupNorm
    gn_kernel<<<(BT * Hc) / 8, 256>>>(yp, y2p, gw, gb);

    // output projection
    sgemm_nt<<<gg, 256>>>(y2p, Wo, out, BT, Cc, Cc);
}

// round 3
// speedup vs baseline: 1.7208x; 1.7208x over previous
#include <cuda_runtime.h>
#include <cuda_bf16.h>
#include <math.h>
#include <stddef.h>
#include <stdint.h>

// Problem constants
#define Bc 8
#define Tc 2048
#define Cc 1024
#define Hc 16
#define Nn 64
#define CHUNKc 256
#define NCHUNK (Tc / CHUNKc)
#define BT (Bc * Tc)                 // 16384
#define BTC ((size_t)Bc * Tc * Cc)   // 16,777,216
#define CC2 (Cc * Cc)                // 1,048,576

// ---------------------------------------------------------------------------
// Scratch (device globals; allocation in kernel_launch is forbidden)
// ---------------------------------------------------------------------------
__device__ float g_r[BTC];
__device__ float g_k[BTC];
__device__ float g_v[BTC];
__device__ float g_y[BTC];
__device__ __nv_bfloat16 g_xrh[BTC], g_xrl[BTC];
__device__ __nv_bfloat16 g_xkh[BTC], g_xkl[BTC];
__device__ __nv_bfloat16 g_xvh[BTC], g_xvl[BTC];
__device__ __nv_bfloat16 g_y2h[BTC], g_y2l[BTC];
__device__ __nv_bfloat16 g_Wrh[CC2], g_Wrl[CC2];
__device__ __nv_bfloat16 g_Wkh[CC2], g_Wkl[CC2];
__device__ __nv_bfloat16 g_Wvh[CC2], g_Wvl[CC2];
__device__ __nv_bfloat16 g_Woh[CC2], g_Wol[CC2];

// ---------------------------------------------------------------------------
// Helpers (family-portable only: cp.async / ldmatrix / mma.sync)
// ---------------------------------------------------------------------------
__device__ __forceinline__ uint32_t smem_u32(const void* p) {
    uint32_t a;
    asm("{ .reg .u64 t; cvta.to.shared.u64 t, %1; cvt.u32.u64 %0, t; }"
        : "=r"(a) : "l"(p));
    return a;
}

#define CP_ASYNC16(sa, gp) \
    asm volatile("cp.async.cg.shared.global [%0], [%1], 16;" :: "r"(sa), "l"(gp) : "memory")
#define CP_COMMIT() asm volatile("cp.async.commit_group;" ::: "memory")
#define CP_WAIT(n)  asm volatile("cp.async.wait_group %0;" :: "n"(n) : "memory")

#define LDSM4(r0, r1, r2, r3, a)                                              \
    asm volatile("ldmatrix.sync.aligned.m8n8.x4.shared.b16 {%0,%1,%2,%3}, [%4];" \
                 : "=r"(r0), "=r"(r1), "=r"(r2), "=r"(r3) : "r"(a))

#define MMA16816(c, a, b)                                                     \
    asm volatile("mma.sync.aligned.m16n8k16.row.col.f32.bf16.bf16.f32 "       \
                 "{%0,%1,%2,%3}, {%4,%5,%6,%7}, {%8,%9}, {%0,%1,%2,%3};"      \
                 : "+f"((c)[0]), "+f"((c)[1]), "+f"((c)[2]), "+f"((c)[3])     \
                 : "r"((a)[0]), "r"((a)[1]), "r"((a)[2]), "r"((a)[3]),        \
                   "r"((b)[0]), "r"((b)[1]))

__device__ __forceinline__ void split2(float f, __nv_bfloat16& h, __nv_bfloat16& l) {
    h = __float2bfloat16(f);
    l = __float2bfloat16(f - __bfloat162float(h));
}

// ---------------------------------------------------------------------------
// Kernel 1: volatility gating + time-shift + maa mixing -> bf16 hi/lo splits
// ---------------------------------------------------------------------------
__global__ __launch_bounds__(256) void prep_kernel(
    const float* __restrict__ x, const float* __restrict__ vol,
    const float* __restrict__ Wvol, const float* __restrict__ bvol,
    const float* __restrict__ mk, const float* __restrict__ mv,
    const float* __restrict__ mr)
{
    size_t idx = (size_t)blockIdx.x * 256 + threadIdx.x;
    int c = (int)(idx & (Cc - 1));
    size_t bt = idx >> 10;
    int t = (int)(bt & (Tc - 1));

    float wv = Wvol[c];
    float bb = bvol[c];
    float g = 1.0f / (1.0f + expf(-(vol[bt] * wv + bb)));
    float xc = x[idx] * g;

    float xp = 0.0f;
    if (t > 0) {
        float gp = 1.0f / (1.0f + expf(-(vol[bt - 1] * wv + bb)));
        xp = x[idx - Cc] * gp;
    }
    float xx = xp - xc;
    __nv_bfloat16 h, l;
    split2(xc + xx * mk[c], h, l); g_xkh[idx] = h; g_xkl[idx] = l;
    split2(xc + xx * mv[c], h, l); g_xvh[idx] = h; g_xvl[idx] = l;
    split2(xc + xx * mr[c], h, l); g_xrh[idx] = h; g_xrl[idx] = l;
}

// ---------------------------------------------------------------------------
// Kernel: fp32 -> bf16 hi/lo split (weights)
// ---------------------------------------------------------------------------
__global__ __launch_bounds__(256) void conv_kernel(
    const float* __restrict__ src, __nv_bfloat16* __restrict__ hi,
    __nv_bfloat16* __restrict__ lo, int n)
{
    int i = blockIdx.x * 256 + threadIdx.x;
    if (i < n) {
        __nv_bfloat16 h, l;
        split2(src[i], h, l);
        hi[i] = h; lo[i] = l;
    }
}

// ---------------------------------------------------------------------------
// Kernel 2: tensor-core GEMM  C[M,1024] = A * W^T via mma.sync, bf16x3 split.
// CTA tile 128x128, BK=32, 8 warps (4m x 2n), warp tile 32x64.
// Smem rows: 32 bf16 + pad -> 80B stride (conflict-free ldmatrix).
// ---------------------------------------------------------------------------
#define GK 1024
#define GN 1024
#define BKq 32
#define NKI (GK / BKq)            // 32
#define TROW 80                    // bytes per smem row (32 bf16 = 64B + 16 pad)
#define TILE_B (128 * TROW)        // 10240
#define STAGE_B (4 * TILE_B)       // Ah, Al, Bh, Bl = 40960
#define SMEM_GEMM (2 * STAGE_B)    // 81920

__device__ __forceinline__ void load_stage(
    uint32_t sbase, const __nv_bfloat16* a0, const __nv_bfloat16* a1,
    const __nv_bfloat16* b0, const __nv_bfloat16* b1, int koff, int tid)
{
    const int row = tid >> 1;
    const int cb = (tid & 1) * 2;
    const __nv_bfloat16* srcs[4] = {a0, a1, b0, b1};
#pragma unroll
    for (int m = 0; m < 4; m++) {
        uint32_t ro = sbase + m * TILE_B + row * TROW;
        const __nv_bfloat16* g = srcs[m] + (size_t)row * GK + koff;
        CP_ASYNC16(ro + (cb + 0) * 16, g + (cb + 0) * 8);
        CP_ASYNC16(ro + (cb + 1) * 16, g + (cb + 1) * 8);
    }
}

__global__ __launch_bounds__(256)
void gemm_mma_bf16x3(const __nv_bfloat16* __restrict__ Ah, const __nv_bfloat16* __restrict__ Al,
                     const __nv_bfloat16* __restrict__ Bh, const __nv_bfloat16* __restrict__ Bl,
                     float* __restrict__ C)
{
    extern __shared__ __align__(16) char smem[];
    const uint32_t sb = smem_u32(smem);

    const int tid = threadIdx.x;
    const int wid = tid >> 5;
    const int lane = tid & 31;
    const int wm = wid >> 1;         // 0..3 -> m offset 32*wm
    const int wn = wid & 1;          // 0..1 -> n offset 64*wn
    const int bm = blockIdx.y * 128;
    const int bn = blockIdx.x * 128;

    const __nv_bfloat16* a0 = Ah + (size_t)bm * GK;
    const __nv_bfloat16* a1 = Al + (size_t)bm * GK;
    const __nv_bfloat16* b0 = Bh + (size_t)bn * GK;
    const __nv_bfloat16* b1 = Bl + (size_t)bn * GK;

    float acc[2][8][4];
#pragma unroll
    for (int i = 0; i < 2; i++)
#pragma unroll
        for (int j = 0; j < 8; j++)
#pragma unroll
            for (int q = 0; q < 4; q++) acc[i][j][q] = 0.0f;

    // ldmatrix per-lane addressing pieces
    const int lr = lane & 15;        // row within 16-row block
    const int lc = lane >> 4;        // k-half (0/1)

    load_stage(sb, a0, a1, b0, b1, 0, tid);
    CP_COMMIT();

    for (int kt = 0; kt < NKI; kt++) {
        const uint32_t cbase = sb + (kt & 1) * STAGE_B;
        if (kt + 1 < NKI) {
            load_stage(sb + ((kt + 1) & 1) * STAGE_B, a0, a1, b0, b1,
                       (kt + 1) * BKq, tid);
            CP_COMMIT();
            CP_WAIT(1);
        } else {
            CP_WAIT(0);
        }
        __syncthreads();

        const uint32_t sAh = cbase;
        const uint32_t sAl = cbase + TILE_B;
        const uint32_t sBh = cbase + 2 * TILE_B;
        const uint32_t sBl = cbase + 3 * TILE_B;

#pragma unroll
        for (int ks = 0; ks < 2; ks++) {
            const uint32_t kb = ks * 32 + lc * 16;

            uint32_t ah[2][4], al[2][4];
#pragma unroll
            for (int am = 0; am < 2; am++) {
                uint32_t roff = (uint32_t)(wm * 32 + am * 16 + lr) * TROW + kb;
                LDSM4(ah[am][0], ah[am][1], ah[am][2], ah[am][3], sAh + roff);
                LDSM4(al[am][0], al[am][1], al[am][2], al[am][3], sAl + roff);
            }

            uint32_t bh[8][2], bl[8][2];
#pragma unroll
            for (int np = 0; np < 4; np++) {
                uint32_t roff = (uint32_t)(wn * 64 + np * 16 + lr) * TROW + kb;
                uint32_t r0, r1, r2, r3;
                LDSM4(r0, r1, r2, r3, sBh + roff);
                bh[2 * np][0] = r0; bh[2 * np][1] = r2;
                bh[2 * np + 1][0] = r1; bh[2 * np + 1][1] = r3;
                LDSM4(r0, r1, r2, r3, sBl + roff);
                bl[2 * np][0] = r0; bl[2 * np][1] = r2;
                bl[2 * np + 1][0] = r1; bl[2 * np + 1][1] = r3;
            }

#pragma unroll
            for (int am = 0; am < 2; am++)
#pragma unroll
                for (int nt = 0; nt < 8; nt++) {
                    MMA16816(acc[am][nt], ah[am], bh[nt]);
                    MMA16816(acc[am][nt], ah[am], bl[nt]);
                    MMA16816(acc[am][nt], al[am], bh[nt]);
                }
        }
        __syncthreads();
    }

    // epilogue: fragment -> gmem fp32
    const int g = lane >> 2;          // row group 0..7
    const int cc = (lane & 3) * 2;    // col pair
#pragma unroll
    for (int am = 0; am < 2; am++)
#pragma unroll
        for (int nt = 0; nt < 8; nt++) {
            int row0 = bm + wm * 32 + am * 16 + g;
            int col = bn + wn * 64 + nt * 8 + cc;
            float2 v0 = make_float2(acc[am][nt][0], acc[am][nt][1]);
            float2 v1 = make_float2(acc[am][nt][2], acc[am][nt][3]);
            *(float2*)(C + (size_t)row0 * GN + col) = v0;
            *(float2*)(C + (size_t)(row0 + 8) * GN + col) = v1;
        }
}

// ---------------------------------------------------------------------------
// Kernel 3: chunked linear-attention recurrence (fp32).
//   y_c    = w * R_c @ (state + K_c^T V_c)
//   state' = w * (state + K_c^T V_c)
// ---------------------------------------------------------------------------
#define ATS 68
__global__ __launch_bounds__(256) void attn_kernel(
    const float* __restrict__ r, const float* __restrict__ k,
    const float* __restrict__ v, float* __restrict__ y,
    const float* __restrict__ time_decay)
{
    extern __shared__ float sm[];
    float* sA = sm;
    float* sV = sm + 64 * ATS;
    float* sM = sm + 2 * 64 * ATS;

    const int bh = blockIdx.x;
    const int b = bh >> 4;
    const int h = bh & 15;
    const float w = expf(-expf(time_decay[h]));

    const int tid = threadIdx.x;
    const int i0 = (tid >> 4) << 2;
    const int j0 = (tid & 15) << 2;
    const size_t base = (size_t)b * Tc * Cc + (size_t)h * Nn;

    float st[4][4];
#pragma unroll
    for (int i = 0; i < 4; i++)
#pragma unroll
        for (int j = 0; j < 4; j++) st[i][j] = 0.0f;

    for (int c = 0; c < NCHUNK; c++) {
        const size_t cbase = base + (size_t)c * CHUNKc * Cc;

        float S[4][4];
#pragma unroll
        for (int i = 0; i < 4; i++)
#pragma unroll
            for (int j = 0; j < 4; j++) S[i][j] = 0.0f;

        for (int tb = 0; tb < 4; tb++) {
            const size_t tbase = cbase + (size_t)tb * 64 * Cc;
#pragma unroll
            for (int i = 0; i < 16; i++) {
                int idx = i * 256 + tid;
                int row = idx >> 6, col = idx & 63;
                sA[row * ATS + col] = k[tbase + (size_t)row * Cc + col];
                sV[row * ATS + col] = v[tbase + (size_t)row * Cc + col];
            }
            __syncthreads();
#pragma unroll 4
            for (int tt = 0; tt < 64; tt++) {
                float kk_[4], vv_[4];
#pragma unroll
                for (int i = 0; i < 4; i++) kk_[i] = sA[tt * ATS + i0 + i];
#pragma unroll
                for (int j = 0; j < 4; j++) vv_[j] = sV[tt * ATS + j0 + j];
#pragma unroll
                for (int i = 0; i < 4; i++)
#pragma unroll
                    for (int j = 0; j < 4; j++) S[i][j] += kk_[i] * vv_[j];
            }
            __syncthreads();
        }

#pragma unroll
        for (int i = 0; i < 4; i++)
#pragma unroll
            for (int j = 0; j < 4; j++) {
                float m = st[i][j] + S[i][j];
                sM[(i0 + i) * ATS + j0 + j] = m;
                st[i][j] = w * m;
            }
        __syncthreads();

        for (int tp = 0; tp < 4; tp++) {
            const size_t tbase = cbase + (size_t)tp * 64 * Cc;
#pragma unroll
            for (int i = 0; i < 16; i++) {
                int idx = i * 256 + tid;
                int row = idx >> 6, col = idx & 63;
                sA[row * ATS + col] = r[tbase + (size_t)row * Cc + col];
            }
            __syncthreads();
            float acc2[4][4];
#pragma unroll
            for (int i = 0; i < 4; i++)
#pragma unroll
                for (int j = 0; j < 4; j++) acc2[i][j] = 0.0f;
#pragma unroll 4
            for (int n = 0; n < 64; n++) {
                float rr[4], mm[4];
#pragma unroll
                for (int i = 0; i < 4; i++) rr[i] = sA[(i0 + i) * ATS + n];
#pragma unroll
                for (int j = 0; j < 4; j++) mm[j] = sM[n * ATS + j0 + j];
#pragma unroll
                for (int i = 0; i < 4; i++)
#pragma unroll
                    for (int j = 0; j < 4; j++) acc2[i][j] += rr[i] * mm[j];
            }
#pragma unroll
            for (int i = 0; i < 4; i++)
#pragma unroll
                for (int j = 0; j < 4; j++)
                    y[tbase + (size_t)(i0 + i) * Cc + j0 + j] = w * acc2[i][j];
            __syncthreads();
        }
    }
}

// ---------------------------------------------------------------------------
// Kernel 4: GroupNorm (H=16 groups of 64) -> bf16 hi/lo splits
// ---------------------------------------------------------------------------
__global__ __launch_bounds__(256) void gn_kernel(
    const float* __restrict__ y,
    const float* __restrict__ gw, const float* __restrict__ gb)
{
    int g = blockIdx.x * 8 + (threadIdx.x >> 5);
    int lane = threadIdx.x & 31;
    size_t basei = (size_t)g * 64;
    float v0 = y[basei + lane];
    float v1 = y[basei + 32 + lane];
    float s = v0 + v1;
    float q = v0 * v0 + v1 * v1;
#pragma unroll
    for (int o = 16; o > 0; o >>= 1) {
        s += __shfl_xor_sync(0xffffffffu, s, o);
        q += __shfl_xor_sync(0xffffffffu, q, o);
    }
    float mean = s * (1.0f / 64.0f);
    float var = q * (1.0f / 64.0f) - mean * mean;
    float rstd = rsqrtf(var + 1e-5f);
    int h = g & 15;
    int cb = h * 64;
    __nv_bfloat16 hh, ll;
    split2((v0 - mean) * rstd * gw[cb + lane] + gb[cb + lane], hh, ll);
    g_y2h[basei + lane] = hh; g_y2l[basei + lane] = ll;
    split2((v1 - mean) * rstd * gw[cb + 32 + lane] + gb[cb + 32 + lane], hh, ll);
    g_y2h[basei + 32 + lane] = hh; g_y2l[basei + 32 + lane] = ll;
}

// ---------------------------------------------------------------------------
// Host launcher
// ---------------------------------------------------------------------------
extern "C" void kernel_launch(void* const* d_in, const int* in_sizes, int n_in,
                              void* d_out, int out_size)
{
    const float* x    = (const float*)d_in[0];
    const float* vol  = (const float*)d_in[1];
    const float* Wvol = (const float*)d_in[2];
    const float* bvol = (const float*)d_in[3];
    const float* mk   = (const float*)d_in[4];
    const float* mv   = (const float*)d_in[5];
    const float* mr   = (const float*)d_in[6];
    const float* td   = (const float*)d_in[7];
    const float* Wk   = (const float*)d_in[8];
    const float* Wv   = (const float*)d_in[9];
    const float* Wr   = (const float*)d_in[10];
    const float* Wo   = (const float*)d_in[11];
    const float* gw   = (const float*)d_in[12];
    const float* gb   = (const float*)d_in[13];
    float* out = (float*)d_out;

    float *rp, *kp, *vp, *yp;
    cudaGetSymbolAddress((void**)&rp, g_r);
    cudaGetSymbolAddress((void**)&kp, g_k);
    cudaGetSymbolAddress((void**)&vp, g_v);
    cudaGetSymbolAddress((void**)&yp, g_y);

    __nv_bfloat16 *xrh, *xrl, *xkh, *xkl, *xvh, *xvl, *y2h, *y2l;
    __nv_bfloat16 *wrh, *wrl, *wkh, *wkl, *wvh, *wvl, *woh, *wol;
    cudaGetSymbolAddress((void**)&xrh, g_xrh); cudaGetSymbolAddress((void**)&xrl, g_xrl);
    cudaGetSymbolAddress((void**)&xkh, g_xkh); cudaGetSymbolAddress((void**)&xkl, g_xkl);
    cudaGetSymbolAddress((void**)&xvh, g_xvh); cudaGetSymbolAddress((void**)&xvl, g_xvl);
    cudaGetSymbolAddress((void**)&y2h, g_y2h); cudaGetSymbolAddress((void**)&y2l, g_y2l);
    cudaGetSymbolAddress((void**)&wrh, g_Wrh); cudaGetSymbolAddress((void**)&wrl, g_Wrl);
    cudaGetSymbolAddress((void**)&wkh, g_Wkh); cudaGetSymbolAddress((void**)&wkl, g_Wkl);
    cudaGetSymbolAddress((void**)&wvh, g_Wvh); cudaGetSymbolAddress((void**)&wvl, g_Wvl);
    cudaGetSymbolAddress((void**)&woh, g_Woh); cudaGetSymbolAddress((void**)&wol, g_Wol);

    // prep: gating + shift + mix -> bf16 splits
    prep_kernel<<<(unsigned)(BTC / 256), 256>>>(x, vol, Wvol, bvol, mk, mv, mr);

    // weight splits
    conv_kernel<<<CC2 / 256, 256>>>(Wr, wrh, wrl, CC2);
    conv_kernel<<<CC2 / 256, 256>>>(Wk, wkh, wkl, CC2);
    conv_kernel<<<CC2 / 256, 256>>>(Wv, wvh, wvl, CC2);
    conv_kernel<<<CC2 / 256, 256>>>(Wo, woh, wol, CC2);

    // tensor-core projections (mma.sync bf16x3)
    cudaFuncSetAttribute(gemm_mma_bf16x3, cudaFuncAttributeMaxDynamicSharedMemorySize,
                         SMEM_GEMM);
    dim3 gg(GN / 128, BT / 128);
    gemm_mma_bf16x3<<<gg, 256, SMEM_GEMM>>>(xrh, xrl, wrh, wrl, rp);
    gemm_mma_bf16x3<<<gg, 256, SMEM_GEMM>>>(xkh, xkl, wkh, wkl, kp);
    gemm_mma_bf16x3<<<gg, 256, SMEM_GEMM>>>(xvh, xvl, wvh, wvl, vp);

    // chunked recurrence
    int attn_smem = 3 * 64 * ATS * sizeof(float);
    cudaFuncSetAttribute(attn_kernel, cudaFuncAttributeMaxDynamicSharedMemorySize,
                         attn_smem);
    attn_kernel<<<Bc * Hc, 256, attn_smem>>>(rp, kp, vp, yp, td);

    // GroupNorm -> bf16 splits
    gn_kernel<<<(BT * Hc) / 8, 256>>>(yp, gw, gb);

    // output projection
    gemm_mma_bf16x3<<<gg, 256, SMEM_GEMM>>>(y2h, y2l, woh, wol, out);
}